// round 2
// baseline (speedup 1.0000x reference)
#include <cuda_runtime.h>
#include <cuda_bf16.h>
#include <math.h>

// ---------------- Problem constants ----------------
#define BB    4
#define TT    1024
#define NTOK  (BB*TT)        // 4096
#define DD    768
#define HH    12
#define HD    64
#define LL    6
#define VV    32000
#define DFF   3072
#define DQKV  2304
#define EPS   1e-5f

// ---------------- Scratch (static device memory; no allocation allowed) ----
__device__ float g_h   [NTOK * DD];     // residual stream
__device__ float g_hn  [NTOK * DD];     // layernormed
__device__ float g_qkv [NTOK * DQKV];   // qkv projections
__device__ float g_attn[NTOK * DD];     // attention context
__device__ float g_ff  [NTOK * DFF];    // MLP hidden

// ---------------- Embedding -------------------------------------------------
__global__ void embed_kernel(const int* __restrict__ x,
                             const float* __restrict__ tok_emb,
                             const float* __restrict__ pos_emb) {
    int row = blockIdx.x;            // token index 0..4095
    int t   = row % TT;
    int id  = x[row];
    const float* te = tok_emb + (size_t)id * DD;
    const float* pe = pos_emb + (size_t)t  * DD;
    float* out = g_h + (size_t)row * DD;
    for (int i = threadIdx.x; i < DD; i += blockDim.x)
        out[i] = te[i] + pe[i];
}

// ---------------- LayerNorm -------------------------------------------------
__device__ __forceinline__ float block_reduce_sum(float v, float* red) {
    int lane = threadIdx.x & 31, wid = threadIdx.x >> 5;
    #pragma unroll
    for (int o = 16; o > 0; o >>= 1) v += __shfl_xor_sync(0xffffffffu, v, o);
    if (lane == 0) red[wid] = v;
    __syncthreads();
    if (wid == 0) {
        float w = (lane < (blockDim.x >> 5)) ? red[lane] : 0.f;
        #pragma unroll
        for (int o = 4; o > 0; o >>= 1) w += __shfl_xor_sync(0xffffffffu, w, o);
        if (lane == 0) red[0] = w;
    }
    __syncthreads();
    float r = red[0];
    __syncthreads();
    return r;
}

// 256 threads per block, one block per token row
__global__ void ln_kernel(const float* __restrict__ xin,
                          const float* __restrict__ sc,
                          const float* __restrict__ bi,
                          float* __restrict__ yout) {
    __shared__ float red[32];
    int row = blockIdx.x;
    const float* xr = xin + (size_t)row * DD;
    float xv[3];
    float s = 0.f;
    #pragma unroll
    for (int i = 0; i < 3; i++) { xv[i] = xr[threadIdx.x + i*256]; s += xv[i]; }
    float mean = block_reduce_sum(s, red) * (1.0f / DD);
    float vs = 0.f;
    #pragma unroll
    for (int i = 0; i < 3; i++) { float d = xv[i] - mean; vs += d * d; }
    float var = block_reduce_sum(vs, red) * (1.0f / DD);
    float rstd = rsqrtf(var + EPS);
    float* yr = yout + (size_t)row * DD;
    #pragma unroll
    for (int i = 0; i < 3; i++) {
        int c = threadIdx.x + i*256;
        yr[c] = (xv[i] - mean) * rstd * sc[c] + bi[c];
    }
}

// ---------------- SGEMM: C[M,N] = A[M,K] @ W[N,K]^T (+bias)(+relu)(+=) ------
// OP: 0 = store, 1 = store+bias, 2 = store+relu(+bias), 3 = C += result+bias
// All of M,N divisible by 64; K divisible by 16.
template<int OP>
__global__ __launch_bounds__(256)
void gemm_kernel(const float* __restrict__ A, const float* __restrict__ W,
                 const float* __restrict__ bias, float* __restrict__ C,
                 int M, int N, int K) {
    __shared__ float As[16][68];
    __shared__ float Ws[16][68];

    int tx = threadIdx.x & 15;       // 0..15 -> N micro
    int ty = threadIdx.x >> 4;       // 0..15 -> M micro
    int bm = blockIdx.y * 64;
    int bn = blockIdx.x * 64;

    int lm = threadIdx.x >> 2;           // 0..63
    int lk = (threadIdx.x & 3) * 4;      // 0,4,8,12
    const float* Aptr = A + (size_t)(bm + lm) * K + lk;
    const float* Wptr = W + (size_t)(bn + lm) * K + lk;

    float acc[4][4];
    #pragma unroll
    for (int i = 0; i < 4; i++)
        #pragma unroll
        for (int j = 0; j < 4; j++) acc[i][j] = 0.f;

    for (int k0 = 0; k0 < K; k0 += 16) {
        float4 a = *(const float4*)(Aptr + k0);
        float4 w = *(const float4*)(Wptr + k0);
        As[lk+0][lm] = a.x; As[lk+1][lm] = a.y; As[lk+2][lm] = a.z; As[lk+3][lm] = a.w;
        Ws[lk+0][lm] = w.x; Ws[lk+1][lm] = w.y; Ws[lk+2][lm] = w.z; Ws[lk+3][lm] = w.w;
        __syncthreads();
        #pragma unroll
        for (int k = 0; k < 16; k++) {
            float av[4], wv[4];
            #pragma unroll
            for (int i = 0; i < 4; i++) av[i] = As[k][ty*4 + i];
            #pragma unroll
            for (int j = 0; j < 4; j++) wv[j] = Ws[k][tx*4 + j];
            #pragma unroll
            for (int i = 0; i < 4; i++)
                #pragma unroll
                for (int j = 0; j < 4; j++)
                    acc[i][j] = fmaf(av[i], wv[j], acc[i][j]);
        }
        __syncthreads();
    }

    #pragma unroll
    for (int i = 0; i < 4; i++) {
        int row = bm + ty*4 + i;
        float* crow = C + (size_t)row * N + bn + tx*4;
        #pragma unroll
        for (int j = 0; j < 4; j++) {
            float v = acc[i][j];
            if (OP >= 1) v += bias[bn + tx*4 + j];
            if (OP == 2) v = fmaxf(v, 0.f);
            if (OP == 3) crow[j] += v;
            else         crow[j]  = v;
        }
    }
}

// ---------------- Causal flash attention ------------------------------------
// grid: (T/64, B*H); block: 64 threads; one query per thread, online softmax.
__global__ __launch_bounds__(64)
void attn_kernel(const float* __restrict__ qkv, float* __restrict__ out) {
    __shared__ float Ks[64][64];
    __shared__ float Vs[64][64];

    int bh = blockIdx.y;
    int b  = bh / HH;
    int h  = bh % HH;
    int qb = blockIdx.x;
    int tid = threadIdx.x;
    int q   = qb * 64 + tid;
    int tok = b * TT + q;

    float qreg[64];
    const float* qptr = qkv + (size_t)tok * DQKV + h * HD;
    #pragma unroll
    for (int d = 0; d < 64; d++) qreg[d] = qptr[d] * 0.125f;  // HD^-0.5

    float acc[64];
    #pragma unroll
    for (int d = 0; d < 64; d++) acc[d] = 0.f;
    float mmax = -INFINITY, lsum = 0.f;

    for (int kt = 0; kt <= qb; kt++) {
        const float* kbase = qkv + (size_t)(b*TT + kt*64) * DQKV + DD       + h*HD;
        const float* vbase = qkv + (size_t)(b*TT + kt*64) * DQKV + 2*DD     + h*HD;
        __syncthreads();
        for (int j = 0; j < 64; j++) {
            Ks[j][tid] = kbase[(size_t)j * DQKV + tid];
            Vs[j][tid] = vbase[(size_t)j * DQKV + tid];
        }
        __syncthreads();

        int jmax = (kt == qb) ? (tid + 1) : 64;
        for (int j = 0; j < jmax; j++) {
            float s = 0.f;
            #pragma unroll
            for (int d = 0; d < 64; d++) s = fmaf(qreg[d], Ks[j][d], s);
            float mnew = fmaxf(mmax, s);
            float corr = __expf(mmax - mnew);
            float p    = __expf(s - mnew);
            lsum = lsum * corr + p;
            #pragma unroll
            for (int d = 0; d < 64; d++)
                acc[d] = fmaf(acc[d], corr, p * Vs[j][d]);
            mmax = mnew;
        }
    }

    float inv = 1.0f / lsum;
    float* optr = out + (size_t)tok * DD + h * HD;
    #pragma unroll
    for (int d = 0; d < 64; d++) optr[d] = acc[d] * inv;
}

// ---------------- Driver ----------------------------------------------------
extern "C" void kernel_launch(void* const* d_in, const int* in_sizes, int n_in,
                              void* d_out, int out_size) {
    (void)in_sizes; (void)n_in; (void)out_size;
    const int*   x       = (const int*)  d_in[0];
    const float* tok_emb = (const float*)d_in[1];
    const float* pos_emb = (const float*)d_in[2];
    const float* qkv_w   = (const float*)d_in[3];
    const float* fc_w    = (const float*)d_in[4];
    const float* fc_b    = (const float*)d_in[5];
    const float* ln1_s   = (const float*)d_in[6];
    const float* ln1_b   = (const float*)d_in[7];
    const float* ln2_s   = (const float*)d_in[8];
    const float* ln2_b   = (const float*)d_in[9];
    const float* ff1_w   = (const float*)d_in[10];
    const float* ff1_b   = (const float*)d_in[11];
    const float* ff2_w   = (const float*)d_in[12];
    const float* ff2_b   = (const float*)d_in[13];
    const float* lnf_s   = (const float*)d_in[14];
    const float* lnf_b   = (const float*)d_in[15];
    const float* out_w   = (const float*)d_in[16];
    const float* out_b   = (const float*)d_in[17];
    float* logits = (float*)d_out;

    float *h, *hn, *qkvb, *attnb, *ffb;
    cudaGetSymbolAddress((void**)&h,     g_h);
    cudaGetSymbolAddress((void**)&hn,    g_hn);
    cudaGetSymbolAddress((void**)&qkvb,  g_qkv);
    cudaGetSymbolAddress((void**)&attnb, g_attn);
    cudaGetSymbolAddress((void**)&ffb,   g_ff);

    embed_kernel<<<NTOK, 256>>>(x, tok_emb, pos_emb);

    for (int l = 0; l < LL; l++) {
        const float* qw  = qkv_w + (size_t)l * DQKV * DD;
        const float* fw  = fc_w  + (size_t)l * DD * DD;
        const float* fb  = fc_b  + (size_t)l * DD;
        const float* f1w = ff1_w + (size_t)l * DFF * DD;
        const float* f1b = ff1_b + (size_t)l * DFF;
        const float* f2w = ff2_w + (size_t)l * DD * DFF;
        const float* f2b = ff2_b + (size_t)l * DD;

        // ln1 -> qkv projection
        ln_kernel<<<NTOK, 256>>>(h, ln1_s + (size_t)l*DD, ln1_b + (size_t)l*DD, hn);
        gemm_kernel<0><<<dim3(DQKV/64, NTOK/64), 256>>>(hn, qw, nullptr, qkvb,
                                                        NTOK, DQKV, DD);
        // causal attention
        attn_kernel<<<dim3(TT/64, BB*HH), 64>>>(qkvb, attnb);
        // output projection + residual add
        gemm_kernel<3><<<dim3(DD/64, NTOK/64), 256>>>(attnb, fw, fb, h,
                                                      NTOK, DD, DD);
        // ln2 -> MLP
        ln_kernel<<<NTOK, 256>>>(h, ln2_s + (size_t)l*DD, ln2_b + (size_t)l*DD, hn);
        gemm_kernel<2><<<dim3(DFF/64, NTOK/64), 256>>>(hn, f1w, f1b, ffb,
                                                       NTOK, DFF, DD);
        gemm_kernel<3><<<dim3(DD/64, NTOK/64), 256>>>(ffb, f2w, f2b, h,
                                                      NTOK, DD, DFF);
    }

    // final layernorm + vocab projection
    ln_kernel<<<NTOK, 256>>>(h, lnf_s, lnf_b, hn);
    gemm_kernel<1><<<dim3(VV/64, NTOK/64), 256>>>(hn, out_w, out_b, logits,
                                                  NTOK, VV, DD);
}

// round 4
// speedup vs baseline: 2.0284x; 2.0284x over previous
#include <cuda_runtime.h>
#include <cuda_bf16.h>
#include <math.h>
#include <stdint.h>

// ---------------- Problem constants ----------------
#define BB    4
#define TT    1024
#define NTOK  (BB*TT)
#define DD    768
#define HH    12
#define HD    64
#define LL    6
#define VV    32000
#define DFF   3072
#define DQKV  2304
#define EPS   1e-5f

// ---------------- Static device buffers ------------
__device__ float g_h   [NTOK * DD];     // residual stream (fp32)
__device__ float g_qkv [NTOK * DQKV];   // qkv projections (fp32)
__device__ __nv_bfloat16 g_xh[NTOK*DD],  g_xl[NTOK*DD];    // LN out hi/lo
__device__ __nv_bfloat16 g_ah[NTOK*DD],  g_al[NTOK*DD];    // attn out hi/lo
__device__ __nv_bfloat16 g_fh[NTOK*DFF], g_fl[NTOK*DFF];   // relu out hi/lo
// bf16 hi/lo weight copies
__device__ __nv_bfloat16 w_qkvh[LL*DQKV*DD], w_qkvl[LL*DQKV*DD];
__device__ __nv_bfloat16 w_fch [LL*DD*DD],   w_fcl [LL*DD*DD];
__device__ __nv_bfloat16 w_f1h [LL*DFF*DD],  w_f1l [LL*DFF*DD];
__device__ __nv_bfloat16 w_f2h [LL*DD*DFF],  w_f2l [LL*DD*DFF];
__device__ __nv_bfloat16 w_oh  [VV*DD],      w_ol  [VV*DD];

// ---------------- PTX helpers (arch-generic only) ---
__device__ __forceinline__ uint32_t smem_to_u32(const void* p) {
    uint32_t a;
    asm("{ .reg .u64 t; cvta.to.shared.u64 t, %1; cvt.u32.u64 %0, t; }"
        : "=r"(a) : "l"(p));
    return a;
}
#define CP_ASYNC16(dst, src) \
    asm volatile("cp.async.cg.shared.global [%0], [%1], 16;" :: "r"(dst), "l"(src))
#define CP_COMMIT asm volatile("cp.async.commit_group;" ::: "memory")
#define CP_WAIT1  asm volatile("cp.async.wait_group 1;" ::: "memory")
#define CP_WAIT0  asm volatile("cp.async.wait_group 0;" ::: "memory")

__device__ __forceinline__ void ldsm4(uint32_t* r, uint32_t addr) {
    asm volatile("ldmatrix.sync.aligned.m8n8.x4.shared.b16 {%0,%1,%2,%3}, [%4];"
        : "=r"(r[0]), "=r"(r[1]), "=r"(r[2]), "=r"(r[3]) : "r"(addr));
}
__device__ __forceinline__ void ldsm2(uint32_t* r, uint32_t addr) {
    asm volatile("ldmatrix.sync.aligned.m8n8.x2.shared.b16 {%0,%1}, [%2];"
        : "=r"(r[0]), "=r"(r[1]) : "r"(addr));
}
__device__ __forceinline__ void mma_bf16(float* d, const uint32_t* a, const uint32_t* b) {
    asm volatile("mma.sync.aligned.m16n8k16.row.col.f32.bf16.bf16.f32 "
        "{%0,%1,%2,%3}, {%4,%5,%6,%7}, {%8,%9}, {%0,%1,%2,%3};"
        : "+f"(d[0]), "+f"(d[1]), "+f"(d[2]), "+f"(d[3])
        : "r"(a[0]), "r"(a[1]), "r"(a[2]), "r"(a[3]), "r"(b[0]), "r"(b[1]));
}

// ---------------- Embedding ------------------------
__global__ void embed_kernel(const int* __restrict__ x,
                             const float* __restrict__ tok_emb,
                             const float* __restrict__ pos_emb) {
    int row = blockIdx.x;
    int t   = row % TT;
    int id  = x[row];
    const float* te = tok_emb + (size_t)id * DD;
    const float* pe = pos_emb + (size_t)t  * DD;
    float* out = g_h + (size_t)row * DD;
    for (int i = threadIdx.x; i < DD; i += blockDim.x)
        out[i] = te[i] + pe[i];
}

// ---------------- fp32 -> bf16 hi/lo split ---------
__global__ void cvt_kernel(const float* __restrict__ s,
                           __nv_bfloat16* __restrict__ hi,
                           __nv_bfloat16* __restrict__ lo, int n4) {
    int i = blockIdx.x * blockDim.x + threadIdx.x;
    int stride = gridDim.x * blockDim.x;
    for (; i < n4; i += stride) {
        float4 v = ((const float4*)s)[i];
        __nv_bfloat16 h0 = __float2bfloat16(v.x);
        __nv_bfloat16 h1 = __float2bfloat16(v.y);
        __nv_bfloat16 h2 = __float2bfloat16(v.z);
        __nv_bfloat16 h3 = __float2bfloat16(v.w);
        __nv_bfloat16 l0 = __float2bfloat16(v.x - __bfloat162float(h0));
        __nv_bfloat16 l1 = __float2bfloat16(v.y - __bfloat162float(h1));
        __nv_bfloat16 l2 = __float2bfloat16(v.z - __bfloat162float(h2));
        __nv_bfloat16 l3 = __float2bfloat16(v.w - __bfloat162float(h3));
        __nv_bfloat162* ph = (__nv_bfloat162*)hi + i*2;
        __nv_bfloat162* pl = (__nv_bfloat162*)lo + i*2;
        ph[0] = __nv_bfloat162(h0, h1); ph[1] = __nv_bfloat162(h2, h3);
        pl[0] = __nv_bfloat162(l0, l1); pl[1] = __nv_bfloat162(l2, l3);
    }
}

// ---------------- LayerNorm -> bf16 hi/lo ----------
__device__ __forceinline__ float block_reduce_sum(float v, float* red) {
    int lane = threadIdx.x & 31, wid = threadIdx.x >> 5;
    #pragma unroll
    for (int o = 16; o > 0; o >>= 1) v += __shfl_xor_sync(0xffffffffu, v, o);
    if (lane == 0) red[wid] = v;
    __syncthreads();
    if (wid == 0) {
        float w = (lane < (blockDim.x >> 5)) ? red[lane] : 0.f;
        #pragma unroll
        for (int o = 4; o > 0; o >>= 1) w += __shfl_xor_sync(0xffffffffu, w, o);
        if (lane == 0) red[0] = w;
    }
    __syncthreads();
    float r = red[0];
    __syncthreads();
    return r;
}

__global__ void ln_kernel(const float* __restrict__ xin,
                          const float* __restrict__ sc,
                          const float* __restrict__ bi,
                          __nv_bfloat16* __restrict__ yh,
                          __nv_bfloat16* __restrict__ yl) {
    __shared__ float red[32];
    int row = blockIdx.x;
    const float* xr = xin + (size_t)row * DD;
    float xv[3];
    float s = 0.f;
    #pragma unroll
    for (int i = 0; i < 3; i++) { xv[i] = xr[threadIdx.x + i*256]; s += xv[i]; }
    float mean = block_reduce_sum(s, red) * (1.0f / DD);
    float vs = 0.f;
    #pragma unroll
    for (int i = 0; i < 3; i++) { float d = xv[i] - mean; vs += d * d; }
    float var = block_reduce_sum(vs, red) * (1.0f / DD);
    float rstd = rsqrtf(var + EPS);
    #pragma unroll
    for (int i = 0; i < 3; i++) {
        int c = threadIdx.x + i*256;
        float v = (xv[i] - mean) * rstd * sc[c] + bi[c];
        __nv_bfloat16 h = __float2bfloat16(v);
        yh[(size_t)row*DD + c] = h;
        yl[(size_t)row*DD + c] = __float2bfloat16(v - __bfloat162float(h));
    }
}

// ---------------- HMMA GEMM (mma.sync, bf16 split) -------------------------
// C[M,N] = (Ah+Al)[M,K] @ (Wh+Wl)[N,K]^T, fp32 accum, 3-term split.
// CTA tile 128x128, 8 warps (2x4), warp tile 64x32, K-chunk 64, 2-stage pipe.
// OP: 0=store fp32, 1=store fp32+bias, 2=C+=v+bias, 3=relu(v+bias)->bf16 hi/lo
#define KC         64
#define TILE_B     16384          // one 128x64 bf16 tile
#define STG_B      (4*TILE_B)     // Ah,Al,Wh,Wl
#define GEMM_SMEM  (2*STG_B)      // 131072

template<int OP>
__global__ __launch_bounds__(256, 1)
void mm_kernel(const __nv_bfloat16* __restrict__ Ah, const __nv_bfloat16* __restrict__ Al,
               const __nv_bfloat16* __restrict__ Wh, const __nv_bfloat16* __restrict__ Wl,
               const float* __restrict__ bias, float* __restrict__ C,
               __nv_bfloat16* __restrict__ Oh, __nv_bfloat16* __restrict__ Ol,
               int N, int K) {
    extern __shared__ char smem[];
    const uint32_t sb = smem_to_u32(smem);
    int tid = threadIdx.x, lane = tid & 31, warp = tid >> 5;
    int wm = warp >> 2;              // 0..1
    int wn = warp & 3;               // 0..3
    int bm = blockIdx.x * 128, bn = blockIdx.y * 128;

    float acc[4][4][4];
    #pragma unroll
    for (int i = 0; i < 4; i++)
        #pragma unroll
        for (int j = 0; j < 4; j++)
            #pragma unroll
            for (int k = 0; k < 4; k++) acc[i][j][k] = 0.f;

    // ---- cp.async mapping: thread -> (row = tid/2, 4 chunks of 16B) ----
    int crow = tid >> 1;
    int cch0 = (tid & 1) * 4;
    const __nv_bfloat16* gA_h = Ah + (size_t)(bm + crow) * K + cch0 * 8;
    const __nv_bfloat16* gA_l = Al + (size_t)(bm + crow) * K + cch0 * 8;
    const __nv_bfloat16* gW_h = Wh + (size_t)(bn + crow) * K + cch0 * 8;
    const __nv_bfloat16* gW_l = Wl + (size_t)(bn + crow) * K + cch0 * 8;
    uint32_t srow = (uint32_t)crow * 128;
    int rsw = crow & 7;

    // ---- ldmatrix per-lane constants ----
    int mat = lane >> 3, r8 = lane & 7;
    int a_kh = mat >> 1;
    uint32_t arowb[4]; int aswz[4];
    #pragma unroll
    for (int ti = 0; ti < 4; ti++) {
        int row = wm*64 + ti*16 + (mat & 1)*8 + r8;
        arowb[ti] = (uint32_t)row * 128;
        aswz[ti]  = row & 7;
    }
    int bl15 = lane & 15;
    int b_kh = bl15 >> 3;
    uint32_t browb[4]; int bswz[4];
    #pragma unroll
    for (int ni = 0; ni < 4; ni++) {
        int row = wn*32 + ni*8 + (bl15 & 7);
        browb[ni] = (uint32_t)row * 128;
        bswz[ni]  = row & 7;
    }

    const int nch = K / KC;

    // ---- prologue: load chunk 0 into stage 0 ----
    {
        uint32_t st = sb;
        #pragma unroll
        for (int i = 0; i < 4; i++) {
            int c = cch0 + i;
            uint32_t soff = srow + (uint32_t)((c ^ rsw) << 4);
            CP_ASYNC16(st + soff,            gA_h + i*8);
            CP_ASYNC16(st + TILE_B + soff,   gA_l + i*8);
            CP_ASYNC16(st + 2*TILE_B + soff, gW_h + i*8);
            CP_ASYNC16(st + 3*TILE_B + soff, gW_l + i*8);
        }
        CP_COMMIT;
    }

    for (int ch = 0; ch < nch; ch++) {
        if (ch + 1 < nch) {
            uint32_t st = sb + ((ch + 1) & 1) * STG_B;
            int k0 = (ch + 1) * KC;
            #pragma unroll
            for (int i = 0; i < 4; i++) {
                int c = cch0 + i;
                uint32_t soff = srow + (uint32_t)((c ^ rsw) << 4);
                CP_ASYNC16(st + soff,            gA_h + k0 + i*8);
                CP_ASYNC16(st + TILE_B + soff,   gA_l + k0 + i*8);
                CP_ASYNC16(st + 2*TILE_B + soff, gW_h + k0 + i*8);
                CP_ASYNC16(st + 3*TILE_B + soff, gW_l + k0 + i*8);
            }
            CP_COMMIT;
            CP_WAIT1;
        } else {
            CP_WAIT0;
        }
        __syncthreads();

        uint32_t stA = sb + (ch & 1) * STG_B;
        uint32_t stW = stA + 2*TILE_B;
        #pragma unroll
        for (int ks = 0; ks < 4; ks++) {
            uint32_t ahf[4][4], alf[4][4];
            #pragma unroll
            for (int ti = 0; ti < 4; ti++) {
                uint32_t off = arowb[ti] + (uint32_t)((((ks << 1) | a_kh) ^ aswz[ti]) << 4);
                ldsm4(ahf[ti], stA + off);
                ldsm4(alf[ti], stA + TILE_B + off);
            }
            uint32_t bhf[4][2], blf[4][2];
            #pragma unroll
            for (int ni = 0; ni < 4; ni++) {
                uint32_t off = browb[ni] + (uint32_t)((((ks << 1) | b_kh) ^ bswz[ni]) << 4);
                ldsm2(bhf[ni], stW + off);
                ldsm2(blf[ni], stW + TILE_B + off);
            }
            #pragma unroll
            for (int ti = 0; ti < 4; ti++)
                #pragma unroll
                for (int ni = 0; ni < 4; ni++) {
                    mma_bf16(acc[ti][ni], ahf[ti], bhf[ni]);
                    mma_bf16(acc[ti][ni], ahf[ti], blf[ni]);
                    mma_bf16(acc[ti][ni], alf[ti], bhf[ni]);
                }
        }
        __syncthreads();
    }

    // ---- epilogue: registers -> gmem ----
    int lr = lane >> 2, lc = (lane & 3) * 2;
    #pragma unroll
    for (int ti = 0; ti < 4; ti++) {
        #pragma unroll
        for (int ni = 0; ni < 4; ni++) {
            int grow = bm + wm*64 + ti*16 + lr;
            int gcol = bn + wn*32 + ni*8 + lc;
            #pragma unroll
            for (int half = 0; half < 2; half++) {
                int r = grow + half*8;
                size_t off = (size_t)r * N + gcol;
                float v0 = acc[ti][ni][half*2 + 0];
                float v1 = acc[ti][ni][half*2 + 1];
                if (OP == 0) {
                    *(float2*)&C[off] = make_float2(v0, v1);
                } else if (OP == 1) {
                    *(float2*)&C[off] = make_float2(v0 + bias[gcol], v1 + bias[gcol+1]);
                } else if (OP == 2) {
                    float2 hcur = *(float2*)&C[off];
                    *(float2*)&C[off] = make_float2(v0 + bias[gcol]   + hcur.x,
                                                    v1 + bias[gcol+1] + hcur.y);
                } else {
                    float f0 = fmaxf(v0 + bias[gcol],   0.f);
                    float f1 = fmaxf(v1 + bias[gcol+1], 0.f);
                    __nv_bfloat16 h0 = __float2bfloat16(f0);
                    __nv_bfloat16 h1 = __float2bfloat16(f1);
                    *(__nv_bfloat162*)&Oh[off] = __nv_bfloat162(h0, h1);
                    __nv_bfloat16 l0 = __float2bfloat16(f0 - __bfloat162float(h0));
                    __nv_bfloat16 l1 = __float2bfloat16(f1 - __bfloat162float(h1));
                    *(__nv_bfloat162*)&Ol[off] = __nv_bfloat162(l0, l1);
                }
            }
        }
    }
}

// ---------------- Causal flash attention -----------
__global__ __launch_bounds__(64)
void attn_kernel(const float* __restrict__ qkv,
                 __nv_bfloat16* __restrict__ oh, __nv_bfloat16* __restrict__ ol) {
    __shared__ float Ks[64][64];
    __shared__ float Vs[64][64];

    int bh = blockIdx.y;
    int b  = bh / HH, h = bh % HH;
    int qb = blockIdx.x;
    int tid = threadIdx.x;
    int tok = b * TT + qb * 64 + tid;

    float4 q4[16];
    const float4* qp = (const float4*)(qkv + (size_t)tok * DQKV + h * HD);
    #pragma unroll
    for (int i = 0; i < 16; i++) {
        q4[i] = qp[i];
        q4[i].x *= 0.125f; q4[i].y *= 0.125f; q4[i].z *= 0.125f; q4[i].w *= 0.125f;
    }
    float4 a4[16];
    #pragma unroll
    for (int i = 0; i < 16; i++) a4[i] = make_float4(0.f, 0.f, 0.f, 0.f);
    float mmax = -INFINITY, lsum = 0.f;

    for (int kt = 0; kt <= qb; kt++) {
        const float* kb = qkv + (size_t)(b*TT + kt*64) * DQKV + DD + h*HD;
        const float* vb = kb + DD;
        __syncthreads();
        for (int j = 0; j < 64; j++) {
            Ks[j][tid] = kb[(size_t)j * DQKV + tid];
            Vs[j][tid] = vb[(size_t)j * DQKV + tid];
        }
        __syncthreads();

        int jmax = (kt == qb) ? (tid + 1) : 64;
        for (int j = 0; j < jmax; j++) {
            const float4* kr = (const float4*)Ks[j];
            float s = 0.f;
            #pragma unroll
            for (int i = 0; i < 16; i++) {
                float4 k = kr[i];
                s += q4[i].x*k.x + q4[i].y*k.y + q4[i].z*k.z + q4[i].w*k.w;
            }
            float p;
            if (s > mmax) {
                float corr = __expf(mmax - s);
                #pragma unroll
                for (int i = 0; i < 16; i++) {
                    a4[i].x *= corr; a4[i].y *= corr; a4[i].z *= corr; a4[i].w *= corr;
                }
                lsum *= corr; mmax = s; p = 1.f;
            } else {
                p = __expf(s - mmax);
            }
            lsum += p;
            const float4* vr = (const float4*)Vs[j];
            #pragma unroll
            for (int i = 0; i < 16; i++) {
                float4 vv = vr[i];
                a4[i].x = fmaf(p, vv.x, a4[i].x);
                a4[i].y = fmaf(p, vv.y, a4[i].y);
                a4[i].z = fmaf(p, vv.z, a4[i].z);
                a4[i].w = fmaf(p, vv.w, a4[i].w);
            }
        }
    }

    float inv = 1.0f / lsum;
    size_t ob = (size_t)tok * DD + h * HD;
    #pragma unroll
    for (int i = 0; i < 16; i++) {
        float f[4] = { a4[i].x*inv, a4[i].y*inv, a4[i].z*inv, a4[i].w*inv };
        #pragma unroll
        for (int c = 0; c < 4; c++) {
            __nv_bfloat16 hh = __float2bfloat16(f[c]);
            oh[ob + i*4 + c] = hh;
            ol[ob + i*4 + c] = __float2bfloat16(f[c] - __bfloat162float(hh));
        }
    }
}

// ---------------- Driver ---------------------------
extern "C" void kernel_launch(void* const* d_in, const int* in_sizes, int n_in,
                              void* d_out, int out_size) {
    (void)in_sizes; (void)n_in; (void)out_size;
    const int*   x       = (const int*)  d_in[0];
    const float* tok_emb = (const float*)d_in[1];
    const float* pos_emb = (const float*)d_in[2];
    const float* qkv_w   = (const float*)d_in[3];
    const float* fc_w    = (const float*)d_in[4];
    const float* fc_b    = (const float*)d_in[5];
    const float* ln1_s   = (const float*)d_in[6];
    const float* ln1_b   = (const float*)d_in[7];
    const float* ln2_s   = (const float*)d_in[8];
    const float* ln2_b   = (const float*)d_in[9];
    const float* ff1_w   = (const float*)d_in[10];
    const float* ff1_b   = (const float*)d_in[11];
    const float* ff2_w   = (const float*)d_in[12];
    const float* ff2_b   = (const float*)d_in[13];
    const float* lnf_s   = (const float*)d_in[14];
    const float* lnf_b   = (const float*)d_in[15];
    const float* out_w   = (const float*)d_in[16];
    const float* out_b   = (const float*)d_in[17];
    float* logits = (float*)d_out;

    // Attribute set is a host-side (non-stream) call; safe every invocation.
    cudaFuncSetAttribute(mm_kernel<0>, cudaFuncAttributeMaxDynamicSharedMemorySize, GEMM_SMEM);
    cudaFuncSetAttribute(mm_kernel<1>, cudaFuncAttributeMaxDynamicSharedMemorySize, GEMM_SMEM);
    cudaFuncSetAttribute(mm_kernel<2>, cudaFuncAttributeMaxDynamicSharedMemorySize, GEMM_SMEM);
    cudaFuncSetAttribute(mm_kernel<3>, cudaFuncAttributeMaxDynamicSharedMemorySize, GEMM_SMEM);

    float *h, *qkvb;
    __nv_bfloat16 *xh, *xl, *ah, *al, *fh, *fl;
    __nv_bfloat16 *qh, *ql, *fch, *fcl, *f1h, *f1l, *f2h, *f2l, *oh, *ol;
    cudaGetSymbolAddress((void**)&h,    g_h);
    cudaGetSymbolAddress((void**)&qkvb, g_qkv);
    cudaGetSymbolAddress((void**)&xh, g_xh);  cudaGetSymbolAddress((void**)&xl, g_xl);
    cudaGetSymbolAddress((void**)&ah, g_ah);  cudaGetSymbolAddress((void**)&al, g_al);
    cudaGetSymbolAddress((void**)&fh, g_fh);  cudaGetSymbolAddress((void**)&fl, g_fl);
    cudaGetSymbolAddress((void**)&qh, w_qkvh); cudaGetSymbolAddress((void**)&ql, w_qkvl);
    cudaGetSymbolAddress((void**)&fch, w_fch); cudaGetSymbolAddress((void**)&fcl, w_fcl);
    cudaGetSymbolAddress((void**)&f1h, w_f1h); cudaGetSymbolAddress((void**)&f1l, w_f1l);
    cudaGetSymbolAddress((void**)&f2h, w_f2h); cudaGetSymbolAddress((void**)&f2l, w_f2l);
    cudaGetSymbolAddress((void**)&oh, w_oh);   cudaGetSymbolAddress((void**)&ol, w_ol);

    // Weight splits (every call; deterministic)
    cvt_kernel<<<2048, 256>>>(qkv_w, qh, ql, LL*DQKV*DD/4);
    cvt_kernel<<<1024, 256>>>(fc_w,  fch, fcl, LL*DD*DD/4);
    cvt_kernel<<<2048, 256>>>(ff1_w, f1h, f1l, LL*DFF*DD/4);
    cvt_kernel<<<2048, 256>>>(ff2_w, f2h, f2l, LL*DD*DFF/4);
    cvt_kernel<<<4096, 256>>>(out_w, oh, ol, VV*DD/4);

    embed_kernel<<<NTOK, 256>>>(x, tok_emb, pos_emb);

    for (int l = 0; l < LL; l++) {
        const __nv_bfloat16* wqh = qh + (size_t)l * DQKV * DD;
        const __nv_bfloat16* wql = ql + (size_t)l * DQKV * DD;
        const __nv_bfloat16* wph = fch + (size_t)l * DD * DD;
        const __nv_bfloat16* wpl = fcl + (size_t)l * DD * DD;
        const __nv_bfloat16* w1h = f1h + (size_t)l * DFF * DD;
        const __nv_bfloat16* w1l = f1l + (size_t)l * DFF * DD;
        const __nv_bfloat16* w2h = f2h + (size_t)l * DD * DFF;
        const __nv_bfloat16* w2l = f2l + (size_t)l * DD * DFF;

        ln_kernel<<<NTOK, 256>>>(h, ln1_s + (size_t)l*DD, ln1_b + (size_t)l*DD, xh, xl);
        mm_kernel<0><<<dim3(NTOK/128, DQKV/128), 256, GEMM_SMEM>>>(
            xh, xl, wqh, wql, nullptr, qkvb, nullptr, nullptr, DQKV, DD);
        attn_kernel<<<dim3(TT/64, BB*HH), 64>>>(qkvb, ah, al);
        mm_kernel<2><<<dim3(NTOK/128, DD/128), 256, GEMM_SMEM>>>(
            ah, al, wph, wpl, fc_b + (size_t)l*DD, h, nullptr, nullptr, DD, DD);
        ln_kernel<<<NTOK, 256>>>(h, ln2_s + (size_t)l*DD, ln2_b + (size_t)l*DD, xh, xl);
        mm_kernel<3><<<dim3(NTOK/128, DFF/128), 256, GEMM_SMEM>>>(
            xh, xl, w1h, w1l, ff1_b + (size_t)l*DFF, nullptr, fh, fl, DFF, DD);
        mm_kernel<2><<<dim3(NTOK/128, DD/128), 256, GEMM_SMEM>>>(
            fh, fl, w2h, w2l, ff2_b + (size_t)l*DD, h, nullptr, nullptr, DD, DFF);
    }

    ln_kernel<<<NTOK, 256>>>(h, lnf_s, lnf_b, xh, xl);
    mm_kernel<1><<<dim3(NTOK/128, VV/128), 256, GEMM_SMEM>>>(
        xh, xl, oh, ol, out_b, logits, nullptr, nullptr, VV, DD);
}